// round 3
// baseline (speedup 1.0000x reference)
#include <cuda_runtime.h>
#include <cuda_bf16.h>
#include <math.h>

// Problem constants
#define BB 4
#define NN 128
#define DD 512
#define HH 8
#define NODES (BB * NN)            // 512
#define EDGES (BB * NN * NN)       // 65536

// ---------------- scratch (static __device__: no allocation allowed) ----------------
__device__ float g_h  [NODES * DD];
__device__ float g_Ae [NODES * DD];   // h @ We1[0:512]   + We1_b
__device__ float g_Be [NODES * DD];   // h @ We1[512:1024]
__device__ float g_Au [NODES * DD];   // h @ Wu1[0:512]   + Wu1_b
__device__ float g_Bu [NODES * DD];   // h @ Wu1[512:1024]
__device__ float g_msg[NODES * DD];   // h @ Wm + Wm_b
__device__ float g_agg[NODES * DD];
__device__ float g_P  [NODES * DD];   // agg @ Wo + Wo_b
__device__ float g_logits[EDGES * HH];
__device__ float g_attn  [EDGES];
__device__ float g_Ee[(size_t)EDGES * DD];   // edge @ We1[1024:1536]; reused as U afterwards
__device__ float g_Eu[(size_t)EDGES * DD];   // edge @ Wu1[1024:1536]

// ---------------- f32x2 helpers ----------------
__device__ __forceinline__ unsigned long long dup2(float x) {
    unsigned long long r;
    unsigned u = __float_as_uint(x);
    asm("mov.b64 %0, {%1, %1};" : "=l"(r) : "r"(u));
    return r;
}
__device__ __forceinline__ void fma2(unsigned long long& c, unsigned long long a,
                                     unsigned long long b) {
    asm("fma.rn.f32x2 %0, %1, %2, %0;" : "+l"(c) : "l"(a), "l"(b));
}
__device__ __forceinline__ void unpack2(unsigned long long v, float& lo, float& hi) {
    unsigned a, b;
    asm("mov.b64 {%0, %1}, %2;" : "=r"(a), "=r"(b) : "l"(v));
    lo = __uint_as_float(a);
    hi = __uint_as_float(b);
}

// ---------------- tiled SGEMM: C[M,N] = A[M,K] @ W[K,N] (+bias) (+residual) ----------
// BM=128 BN=128 BK=16, 256 threads, 8x8 per-thread via packed fma.rn.f32x2.
// M % 128 == 0, N % 128 == 0, K % 16 == 0 (all true here).
__global__ __launch_bounds__(256) void sgemm_k(
    const float* __restrict__ A, const float* __restrict__ W,
    const float* __restrict__ bias, const float* __restrict__ R,
    float* __restrict__ C, int M, int K, int Nw)
{
    __shared__ __align__(16) float As[16][128];
    __shared__ __align__(16) float Bs[16][128];

    const int tid = threadIdx.x;
    const int m0 = blockIdx.y * 128;
    const int n0 = blockIdx.x * 128;
    const int tx = tid & 15;      // 16 col groups
    const int ty = tid >> 4;      // 16 row groups

    unsigned long long acc[8][4];
#pragma unroll
    for (int m = 0; m < 8; m++)
#pragma unroll
        for (int j = 0; j < 4; j++) acc[m][j] = 0ull;

    const int ar = tid >> 2;            // 0..63
    const int ac = (tid & 3) * 4;       // 0,4,8,12
    const int br = tid >> 5;            // 0..7
    const int bc = (tid & 31) * 4;      // 0..124

    const float* Ag = A + (size_t)(m0 + ar) * K + ac;
    const float* Bg = W + (size_t)br * Nw + n0 + bc;

    for (int kt = 0; kt < K; kt += 16) {
        float4 a0 = *(const float4*)(Ag + kt);
        float4 a1 = *(const float4*)(Ag + (size_t)64 * K + kt);
        float4 b0 = *(const float4*)(Bg + (size_t)kt * Nw);
        float4 b1 = *(const float4*)(Bg + (size_t)(kt + 8) * Nw);

        As[ac + 0][ar] = a0.x; As[ac + 1][ar] = a0.y;
        As[ac + 2][ar] = a0.z; As[ac + 3][ar] = a0.w;
        As[ac + 0][ar + 64] = a1.x; As[ac + 1][ar + 64] = a1.y;
        As[ac + 2][ar + 64] = a1.z; As[ac + 3][ar + 64] = a1.w;
        *(float4*)&Bs[br][bc]     = b0;
        *(float4*)&Bs[br + 8][bc] = b1;
        __syncthreads();

#pragma unroll
        for (int k = 0; k < 16; k++) {
            float4 av0 = *(const float4*)&As[k][ty * 8];
            float4 av1 = *(const float4*)&As[k][ty * 8 + 4];
            const unsigned long long* bp =
                (const unsigned long long*)&Bs[k][tx * 8];
            unsigned long long bv0 = bp[0], bv1 = bp[1], bv2 = bp[2], bv3 = bp[3];
            float am[8] = {av0.x, av0.y, av0.z, av0.w, av1.x, av1.y, av1.z, av1.w};
#pragma unroll
            for (int m = 0; m < 8; m++) {
                unsigned long long ad = dup2(am[m]);
                fma2(acc[m][0], ad, bv0);
                fma2(acc[m][1], ad, bv1);
                fma2(acc[m][2], ad, bv2);
                fma2(acc[m][3], ad, bv3);
            }
        }
        __syncthreads();
    }

    // epilogue
#pragma unroll
    for (int m = 0; m < 8; m++) {
        int row = m0 + ty * 8 + m;
        int col = n0 + tx * 8;
        size_t base = (size_t)row * Nw + col;
        float out[8];
#pragma unroll
        for (int j = 0; j < 4; j++) unpack2(acc[m][j], out[2 * j], out[2 * j + 1]);
        if (bias) {
            float4 bA = *(const float4*)&bias[col];
            float4 bBv = *(const float4*)&bias[col + 4];
            out[0] += bA.x; out[1] += bA.y; out[2] += bA.z; out[3] += bA.w;
            out[4] += bBv.x; out[5] += bBv.y; out[6] += bBv.z; out[7] += bBv.w;
        }
        if (R) {
            float4 r0 = *(const float4*)&R[base];
            float4 r1 = *(const float4*)&R[base + 4];
            out[0] += r0.x; out[1] += r0.y; out[2] += r0.z; out[3] += r0.w;
            out[4] += r1.x; out[5] += r1.y; out[6] += r1.z; out[7] += r1.w;
        }
        *(float4*)&C[base]     = make_float4(out[0], out[1], out[2], out[3]);
        *(float4*)&C[base + 4] = make_float4(out[4], out[5], out[6], out[7]);
    }
}

// ---------------- edge attention logits: one warp per edge ----------------
// e = leaky_relu(Ae[i] + Be[j] + Ee[edge], 0.2); logits = e @ We2 + We2_b
__global__ __launch_bounds__(256) void logits_kernel(
    const float* __restrict__ We2_w, const float* __restrict__ We2_b,
    float* __restrict__ logits)
{
    int warp = (blockIdx.x * blockDim.x + threadIdx.x) >> 5;
    int lane = threadIdx.x & 31;
    if (warp >= EDGES) return;
    int r  = warp;
    int bi = r >> 7;                 // b*N + i
    int b  = r >> 14;
    int bj = (b << 7) + (r & 127);   // b*N + j

    const float* ae = g_Ae + (size_t)bi * DD;
    const float* be = g_Be + (size_t)bj * DD;
    const float* ee = g_Ee + (size_t)r * DD;

    float acc[HH];
#pragma unroll
    for (int h = 0; h < HH; h++) acc[h] = 0.f;

    for (int d = lane; d < DD; d += 32) {
        float x = ae[d] + be[d] + ee[d];
        float e = (x > 0.f) ? x : 0.2f * x;
        const float* wr = We2_w + (size_t)d * HH;
        float4 w0 = *(const float4*)wr;
        float4 w1 = *(const float4*)(wr + 4);
        acc[0] += e * w0.x; acc[1] += e * w0.y; acc[2] += e * w0.z; acc[3] += e * w0.w;
        acc[4] += e * w1.x; acc[5] += e * w1.y; acc[6] += e * w1.z; acc[7] += e * w1.w;
    }
#pragma unroll
    for (int h = 0; h < HH; h++) {
#pragma unroll
        for (int off = 16; off; off >>= 1)
            acc[h] += __shfl_xor_sync(0xffffffffu, acc[h], off);
    }
    if (lane < HH) logits[(size_t)r * HH + lane] = acc[lane] + We2_b[lane];
}

// ---------------- softmax over j, * adj, mean over heads ----------------
__global__ __launch_bounds__(256) void attn_kernel(
    const float* __restrict__ adj)
{
    int bi = blockIdx.x;              // b*N + i
    __shared__ float L[NN][HH];
    __shared__ float mx[HH], sm[HH];
    int tid = threadIdx.x;
    for (int t = tid; t < NN * HH; t += 256)
        ((float*)L)[t] = g_logits[(size_t)bi * NN * HH + t];
    __syncthreads();
    if (tid < HH) {
        float m = -1e30f;
        for (int j = 0; j < NN; j++) m = fmaxf(m, L[j][tid]);
        float s = 0.f;
        for (int j = 0; j < NN; j++) s += expf(L[j][tid] - m);
        mx[tid] = m; sm[tid] = 1.f / s;
    }
    __syncthreads();
    if (tid < NN) {
        float acc = 0.f;
#pragma unroll
        for (int h = 0; h < HH; h++) acc += expf(L[tid][h] - mx[h]) * sm[h];
        g_attn[(size_t)bi * NN + tid] = adj[(size_t)bi * NN + tid] * acc * (1.f / HH);
    }
}

// ---------------- aggregated = attn_mean @ messages (batched) ----------------
__global__ __launch_bounds__(256) void agg_kernel()
{
    int bi = blockIdx.x;
    int b  = bi >> 7;
    __shared__ float a[NN];
    int tid = threadIdx.x;
    if (tid < NN) a[tid] = g_attn[(size_t)bi * NN + tid];
    __syncthreads();
    for (int d = tid; d < DD; d += 256) {
        float acc = 0.f;
#pragma unroll 4
        for (int j = 0; j < NN; j++)
            acc += a[j] * g_msg[(size_t)((b << 7) + j) * DD + d];
        g_agg[(size_t)bi * DD + d] = acc;
    }
}

// ---------------- LayerNorm(node + P) ----------------
__global__ __launch_bounds__(256) void ln_kernel(
    const float* __restrict__ node, const float* __restrict__ gam,
    const float* __restrict__ bet, float* __restrict__ out)
{
    int bi = blockIdx.x;
    int tid = threadIdx.x;
    size_t base = (size_t)bi * DD;
    float x0 = node[base + tid]       + g_P[base + tid];
    float x1 = node[base + tid + 256] + g_P[base + tid + 256];
    float s  = x0 + x1;
    float sq = x0 * x0 + x1 * x1;
    __shared__ float ss[8], qq[8];
#pragma unroll
    for (int o = 16; o; o >>= 1) {
        s  += __shfl_xor_sync(0xffffffffu, s,  o);
        sq += __shfl_xor_sync(0xffffffffu, sq, o);
    }
    if ((tid & 31) == 0) { ss[tid >> 5] = s; qq[tid >> 5] = sq; }
    __syncthreads();
    float tot = 0.f, totq = 0.f;
#pragma unroll
    for (int i = 0; i < 8; i++) { tot += ss[i]; totq += qq[i]; }
    float mu  = tot * (1.f / DD);
    float var = totq * (1.f / DD) - mu * mu;
    float inv = rsqrtf(var + 1e-5f);
    out[base + tid]       = (x0 - mu) * inv * gam[tid]       + bet[tid];
    out[base + tid + 256] = (x1 - mu) * inv * gam[tid + 256] + bet[tid + 256];
}

// ---------------- U = gelu(Au[i] + Bu[j] + Eu[edge]) -> g_Ee (reused) ------------
__global__ __launch_bounds__(256) void u_kernel()
{
    int v = blockIdx.x * blockDim.x + threadIdx.x;   // float4 index
    // DD/4 = 128 float4 per edge row
    int r  = v >> 7;
    int d4 = v & 127;
    int bi = r >> 7;
    int b  = r >> 14;
    int bj = (b << 7) + (r & 127);

    const float4* au = (const float4*)(g_Au + (size_t)bi * DD) + d4;
    const float4* bu = (const float4*)(g_Bu + (size_t)bj * DD) + d4;
    const float4* eu = (const float4*)(g_Eu + (size_t)r  * DD) + d4;
    float4 A = *au, Bv = *bu, E = *eu;
    float x[4] = {A.x + Bv.x + E.x, A.y + Bv.y + E.y,
                  A.z + Bv.z + E.z, A.w + Bv.w + E.w};
    float o[4];
#pragma unroll
    for (int t = 0; t < 4; t++)
        o[t] = 0.5f * x[t] * (1.f + erff(x[t] * 0.70710678118654752f));
    ((float4*)(g_Ee + (size_t)r * DD))[d4] = make_float4(o[0], o[1], o[2], o[3]);
}

// ---------------- host launch ----------------
static float* sym(const void* symbol) {
    void* p = nullptr;
    cudaGetSymbolAddress(&p, symbol);
    return (float*)p;
}

extern "C" void kernel_launch(void* const* d_in, const int* in_sizes, int n_in,
                              void* d_out, int out_size)
{
    const float* node  = (const float*)d_in[0];
    const float* edge  = (const float*)d_in[1];
    const float* adj   = (const float*)d_in[2];
    const float* Wn_w  = (const float*)d_in[3];
    const float* Wn_b  = (const float*)d_in[4];
    const float* We1_w = (const float*)d_in[5];
    const float* We1_b = (const float*)d_in[6];
    const float* We2_w = (const float*)d_in[7];
    const float* We2_b = (const float*)d_in[8];
    const float* Wm_w  = (const float*)d_in[9];
    const float* Wm_b  = (const float*)d_in[10];
    const float* Wu1_w = (const float*)d_in[11];
    const float* Wu1_b = (const float*)d_in[12];
    const float* Wu2_w = (const float*)d_in[13];
    const float* Wu2_b = (const float*)d_in[14];
    const float* Wo_w  = (const float*)d_in[15];
    const float* Wo_b  = (const float*)d_in[16];
    const float* ln_g  = (const float*)d_in[17];
    const float* ln_b  = (const float*)d_in[18];

    float* out_nodes = (float*)d_out;
    float* out_edges = out_nodes + (size_t)NODES * DD;

    float* ph   = sym(g_h);
    float* pAe  = sym(g_Ae);
    float* pBe  = sym(g_Be);
    float* pAu  = sym(g_Au);
    float* pBu  = sym(g_Bu);
    float* pMsg = sym(g_msg);
    float* pAgg = sym(g_agg);
    float* pP   = sym(g_P);
    float* pLog = sym(g_logits);
    float* pEe  = sym(g_Ee);
    float* pEu  = sym(g_Eu);

    dim3 gSmall(DD / 128, NODES / 128);      // (4, 4)
    dim3 gBig  (DD / 128, EDGES / 128);      // (4, 512)

    // node projections
    sgemm_k<<<gSmall, 256>>>(node, Wn_w, Wn_b, nullptr, ph, NODES, DD, DD);
    sgemm_k<<<gSmall, 256>>>(ph, We1_w,                We1_b,  nullptr, pAe, NODES, DD, DD);
    sgemm_k<<<gSmall, 256>>>(ph, We1_w + 512 * DD,     nullptr, nullptr, pBe, NODES, DD, DD);
    sgemm_k<<<gSmall, 256>>>(ph, Wu1_w,                Wu1_b,  nullptr, pAu, NODES, DD, DD);
    sgemm_k<<<gSmall, 256>>>(ph, Wu1_w + 512 * DD,     nullptr, nullptr, pBu, NODES, DD, DD);
    sgemm_k<<<gSmall, 256>>>(ph, Wm_w,                 Wm_b,   nullptr, pMsg, NODES, DD, DD);

    // per-edge projections (the big GEMMs)
    sgemm_k<<<gBig, 256>>>(edge, We1_w + 1024 * DD, nullptr, nullptr, pEe, EDGES, DD, DD);
    sgemm_k<<<gBig, 256>>>(edge, Wu1_w + 1024 * DD, nullptr, nullptr, pEu, EDGES, DD, DD);

    // attention logits -> softmax -> aggregation -> node update
    logits_kernel<<<EDGES / 8, 256>>>(We2_w, We2_b, pLog);
    attn_kernel<<<NODES, 256>>>(adj);
    agg_kernel<<<NODES, 256>>>();
    sgemm_k<<<gSmall, 256>>>(pAgg, Wo_w, Wo_b, nullptr, pP, NODES, DD, DD);
    ln_kernel<<<NODES, 256>>>(node, ln_g, ln_b, out_nodes);

    // edge update: U = gelu(...), out = edge + U @ Wu2 + b
    u_kernel<<<(EDGES * (DD / 4)) / 256, 256>>>();
    sgemm_k<<<gBig, 256>>>(pEe, Wu2_w, Wu2_b, edge, out_edges, EDGES, DD, DD);
}

// round 8
// speedup vs baseline: 3.2587x; 3.2587x over previous
#include <cuda_runtime.h>
#include <cuda_bf16.h>
#include <math.h>
#include <stdint.h>

// ---------------- problem constants ----------------
#define BB 4
#define NN 128
#define DD 512
#define HH 8
#define NODES (BB * NN)            // 512
#define EDGES (BB * NN * NN)       // 65536
#define KDIM 512

// ---------------- GEMM tile config ----------------
#define BM 128
#define BN 128
#define BK 16
#define SROW 20                     // padded floats per smem row (16 used + 4 pad)

// ---------------- scratch (static __device__) ----------------
__device__ __align__(1024) float g_h      [NODES * DD];
__device__ __align__(1024) float g_nodecat[NODES * 2560];   // Ae|Be|Au|Bu|msg
__device__ __align__(1024) float g_agg    [NODES * DD];
__device__ __align__(1024) float g_P      [NODES * DD];
__device__ __align__(1024) float g_logits [EDGES * HH];
__device__ __align__(1024) float g_attn   [EDGES];
__device__ __align__(1024) float g_big    [(size_t)EDGES * 1024];  // Ee | Eu
__device__ __align__(1024) float g_U      [(size_t)EDGES * DD];
__device__ __align__(1024) float g_Wt_big [1024 * DD];
__device__ __align__(1024) float g_Wt_node[2560 * DD];
__device__ __align__(1024) float g_Wt_n   [DD * DD];
__device__ __align__(1024) float g_Wt_o   [DD * DD];
__device__ __align__(1024) float g_Wt_u2  [DD * DD];
__device__ __align__(1024) float g_bnode  [2560];

// ---------------- helpers ----------------
__device__ __forceinline__ uint32_t smem_u32(const void* p) {
    uint32_t a;
    asm("{ .reg .u64 t; cvta.to.shared.u64 t, %1; cvt.u32.u64 %0, t; }" : "=r"(a) : "l"(p));
    return a;
}
__device__ __forceinline__ float rna_tf32(float x) {
    float r;
    asm("cvt.rna.tf32.f32 %0, %1;" : "=f"(r) : "f"(x));
    return r;
}
__device__ __forceinline__ uint32_t rna_u(float x) {
    uint32_t r;
    asm("cvt.rna.tf32.f32 %0, %1;" : "=r"(r) : "f"(x));
    return r;
}
__device__ __forceinline__ void cp16(uint32_t s, const float* g) {
    uint64_t ga = __cvta_generic_to_global(g);
    asm volatile("cp.async.cg.shared.global [%0], [%1], 16;" :: "r"(s), "l"(ga));
}
#define CP_COMMIT() asm volatile("cp.async.commit_group;" ::: "memory")
#define CP_WAIT0()  asm volatile("cp.async.wait_group 0;" ::: "memory")

__device__ __forceinline__ void mma8(float* c, const uint32_t* a, const uint32_t* b) {
    asm volatile(
        "mma.sync.aligned.m16n8k8.row.col.f32.tf32.tf32.f32 "
        "{%0,%1,%2,%3}, {%4,%5,%6,%7}, {%8,%9}, {%0,%1,%2,%3};"
        : "+f"(c[0]), "+f"(c[1]), "+f"(c[2]), "+f"(c[3])
        : "r"(a[0]), "r"(a[1]), "r"(a[2]), "r"(a[3]), "r"(b[0]), "r"(b[1]));
}

// ---------------- TF32 tensor-core GEMM ----------------
// C[M, Ntot] = A[M,512] @ Wt[Ntot,512]^T  (+bias) (+resid)
// A raw fp32 (rna applied in-register); Wt pre-rounded.
__global__ __launch_bounds__(256, 2) void gemm_mma(
    const float* __restrict__ A, const float* __restrict__ Bw,
    float* __restrict__ C, int ldc,
    const float* __restrict__ bias, const float* __restrict__ resid)
{
    __shared__ float sA[2][BM * SROW];
    __shared__ float sB[2][BN * SROW];

    const int tid = threadIdx.x;
    const int wid = tid >> 5, lane = tid & 31;
    const int g = lane >> 2, tig = lane & 3;
    const int m0 = blockIdx.y * BM, n0 = blockIdx.x * BN;
    const int wm = (wid & 1) * 64, wn = (wid >> 1) * 32;

    float acc[4][4][4];
#pragma unroll
    for (int mi = 0; mi < 4; mi++)
#pragma unroll
        for (int ni = 0; ni < 4; ni++)
#pragma unroll
            for (int j = 0; j < 4; j++) acc[mi][ni][j] = 0.f;

    const uint32_t sAa = smem_u32(sA);
    const uint32_t sBa = smem_u32(sB);
    const int lr = tid >> 2;             // 0..63
    const int lc = (tid & 3) * 4;        // 0,4,8,12

    // prefetch k-tile 0
#pragma unroll
    for (int i = 0; i < 2; i++) {
        int row = lr + i * 64;
        cp16(sAa + (uint32_t)(row * SROW + lc) * 4, A + (size_t)(m0 + row) * KDIM + lc);
        cp16(sBa + (uint32_t)(row * SROW + lc) * 4, Bw + (size_t)(n0 + row) * KDIM + lc);
    }
    CP_COMMIT();

    for (int it = 0; it < KDIM / BK; it++) {
        CP_WAIT0();
        __syncthreads();
        if (it + 1 < KDIM / BK) {
            int buf = (it + 1) & 1;
            int kt = (it + 1) * BK;
#pragma unroll
            for (int i = 0; i < 2; i++) {
                int row = lr + i * 64;
                cp16(sAa + (uint32_t)(buf * BM * SROW + row * SROW + lc) * 4,
                     A + (size_t)(m0 + row) * KDIM + kt + lc);
                cp16(sBa + (uint32_t)(buf * BN * SROW + row * SROW + lc) * 4,
                     Bw + (size_t)(n0 + row) * KDIM + kt + lc);
            }
            CP_COMMIT();
        }
        const float* a = sA[it & 1];
        const float* b = sB[it & 1];
#pragma unroll
        for (int ks = 0; ks < 2; ks++) {
            const int k0 = ks * 8;
            uint32_t af[4][4], bf[4][2];
#pragma unroll
            for (int mi = 0; mi < 4; mi++) {
                int r = wm + mi * 16 + g;
                af[mi][0] = rna_u(a[r * SROW + k0 + tig]);
                af[mi][1] = rna_u(a[(r + 8) * SROW + k0 + tig]);
                af[mi][2] = rna_u(a[r * SROW + k0 + tig + 4]);
                af[mi][3] = rna_u(a[(r + 8) * SROW + k0 + tig + 4]);
            }
#pragma unroll
            for (int ni = 0; ni < 4; ni++) {
                int c = wn + ni * 8 + g;
                bf[ni][0] = __float_as_uint(b[c * SROW + k0 + tig]);
                bf[ni][1] = __float_as_uint(b[c * SROW + k0 + tig + 4]);
            }
#pragma unroll
            for (int mi = 0; mi < 4; mi++)
#pragma unroll
                for (int ni = 0; ni < 4; ni++)
                    mma8(acc[mi][ni], af[mi], bf[ni]);
        }
    }

    // epilogue
#pragma unroll
    for (int mi = 0; mi < 4; mi++) {
#pragma unroll
        for (int ni = 0; ni < 4; ni++) {
            int row = m0 + wm + mi * 16 + g;
            int col = n0 + wn + ni * 8 + 2 * tig;
            float2 v0 = make_float2(acc[mi][ni][0], acc[mi][ni][1]);
            float2 v1 = make_float2(acc[mi][ni][2], acc[mi][ni][3]);
            if (bias) {
                float bx = bias[col], by = bias[col + 1];
                v0.x += bx; v0.y += by;
                v1.x += bx; v1.y += by;
            }
            size_t o0 = (size_t)row * ldc + col;
            size_t o1 = (size_t)(row + 8) * ldc + col;
            if (resid) {
                float2 r0 = *(const float2*)&resid[o0];
                float2 r1 = *(const float2*)&resid[o1];
                v0.x += r0.x; v0.y += r0.y;
                v1.x += r1.x; v1.y += r1.y;
            }
            *(float2*)&C[o0] = v0;
            *(float2*)&C[o1] = v1;
        }
    }
}

// ---------------- weight prep: transpose 512x512 sections + rna round ----------------
__global__ void prep_w(const float* We1, const float* Wu1, const float* Wm,
                       const float* Wn, const float* Wo, const float* Wu2)
{
    int z = blockIdx.z;
    const float* src; float* dst;
    switch (z) {
        case 0: src = We1 + 1024 * DD; dst = g_Wt_big;              break;
        case 1: src = Wu1 + 1024 * DD; dst = g_Wt_big + 512 * DD;   break;
        case 2: src = We1;             dst = g_Wt_node;             break;
        case 3: src = We1 + 512 * DD;  dst = g_Wt_node + 512 * DD;  break;
        case 4: src = Wu1;             dst = g_Wt_node + 1024 * DD; break;
        case 5: src = Wu1 + 512 * DD;  dst = g_Wt_node + 1536 * DD; break;
        case 6: src = Wm;              dst = g_Wt_node + 2048 * DD; break;
        case 7: src = Wn;              dst = g_Wt_n;  break;
        case 8: src = Wo;              dst = g_Wt_o;  break;
        default: src = Wu2;            dst = g_Wt_u2; break;
    }
    __shared__ float t[32][33];
    int bx = blockIdx.x * 32, by = blockIdx.y * 32;
    for (int i = threadIdx.y; i < 32; i += 8)
        t[i][threadIdx.x] = src[(size_t)(by + i) * DD + bx + threadIdx.x];
    __syncthreads();
    for (int i = threadIdx.y; i < 32; i += 8)
        dst[(size_t)(bx + i) * DD + by + threadIdx.x] = rna_tf32(t[threadIdx.x][i]);
}

__global__ void bias_cat(const float* We1_b, const float* Wu1_b, const float* Wm_b)
{
    int i = blockIdx.x * blockDim.x + threadIdx.x;
    if (i >= 2560) return;
    float v = 0.f;
    if (i < 512) v = We1_b[i];
    else if (i >= 1024 && i < 1536) v = Wu1_b[i - 1024];
    else if (i >= 2048) v = Wm_b[i - 2048];
    g_bnode[i] = v;
}

// ---------------- edge attention logits: one warp per edge ----------------
__global__ __launch_bounds__(256) void logits_kernel(
    const float* __restrict__ We2_w, const float* __restrict__ We2_b)
{
    int warp = (blockIdx.x * blockDim.x + threadIdx.x) >> 5;
    int lane = threadIdx.x & 31;
    if (warp >= EDGES) return;
    int r  = warp;
    int bi = r >> 7;
    int b  = r >> 14;
    int bj = (b << 7) + (r & 127);

    const float* ae = g_nodecat + (size_t)bi * 2560;         // Ae
    const float* be = g_nodecat + (size_t)bj * 2560 + 512;   // Be
    const float* ee = g_big + (size_t)r * 1024;              // Ee

    float acc[HH];
#pragma unroll
    for (int h = 0; h < HH; h++) acc[h] = 0.f;

    for (int d = lane; d < DD; d += 32) {
        float x = ae[d] + be[d] + ee[d];
        float e = (x > 0.f) ? x : 0.2f * x;
        const float* wr = We2_w + (size_t)d * HH;
        float4 w0 = *(const float4*)wr;
        float4 w1 = *(const float4*)(wr + 4);
        acc[0] += e * w0.x; acc[1] += e * w0.y; acc[2] += e * w0.z; acc[3] += e * w0.w;
        acc[4] += e * w1.x; acc[5] += e * w1.y; acc[6] += e * w1.z; acc[7] += e * w1.w;
    }
#pragma unroll
    for (int h = 0; h < HH; h++) {
#pragma unroll
        for (int off = 16; off; off >>= 1)
            acc[h] += __shfl_xor_sync(0xffffffffu, acc[h], off);
    }
    if (lane < HH) g_logits[(size_t)r * HH + lane] = acc[lane] + We2_b[lane];
}

// ---------------- softmax over j, * adj, mean over heads ----------------
__global__ __launch_bounds__(256) void attn_kernel(const float* __restrict__ adj)
{
    int bi = blockIdx.x;
    __shared__ float L[NN][HH];
    __shared__ float mx[HH], sm[HH];
    int tid = threadIdx.x;
    for (int t = tid; t < NN * HH; t += 256)
        ((float*)L)[t] = g_logits[(size_t)bi * NN * HH + t];
    __syncthreads();
    if (tid < HH) {
        float m = -1e30f;
        for (int j = 0; j < NN; j++) m = fmaxf(m, L[j][tid]);
        float s = 0.f;
        for (int j = 0; j < NN; j++) s += expf(L[j][tid] - m);
        mx[tid] = m; sm[tid] = 1.f / s;
    }
    __syncthreads();
    if (tid < NN) {
        float acc = 0.f;
#pragma unroll
        for (int h = 0; h < HH; h++) acc += expf(L[tid][h] - mx[h]) * sm[h];
        g_attn[(size_t)bi * NN + tid] = adj[(size_t)bi * NN + tid] * acc * (1.f / HH);
    }
}

// ---------------- aggregated = attn_mean @ messages ----------------
__global__ __launch_bounds__(256) void agg_kernel()
{
    int bi = blockIdx.x;
    int b  = bi >> 7;
    __shared__ float a[NN];
    int tid = threadIdx.x;
    if (tid < NN) a[tid] = g_attn[(size_t)bi * NN + tid];
    __syncthreads();
    for (int d = tid; d < DD; d += 256) {
        float acc = 0.f;
#pragma unroll 4
        for (int j = 0; j < NN; j++)
            acc += a[j] * g_nodecat[(size_t)((b << 7) + j) * 2560 + 2048 + d];
        g_agg[(size_t)bi * DD + d] = acc;
    }
}

// ---------------- LayerNorm(node + P) ----------------
__global__ __launch_bounds__(256) void ln_kernel(
    const float* __restrict__ node, const float* __restrict__ gam,
    const float* __restrict__ bet, float* __restrict__ out)
{
    int bi = blockIdx.x;
    int tid = threadIdx.x;
    size_t base = (size_t)bi * DD;
    float x0 = node[base + tid]       + g_P[base + tid];
    float x1 = node[base + tid + 256] + g_P[base + tid + 256];
    float s  = x0 + x1;
    float sq = x0 * x0 + x1 * x1;
    __shared__ float ss[8], qq[8];
#pragma unroll
    for (int o = 16; o; o >>= 1) {
        s  += __shfl_xor_sync(0xffffffffu, s,  o);
        sq += __shfl_xor_sync(0xffffffffu, sq, o);
    }
    if ((tid & 31) == 0) { ss[tid >> 5] = s; qq[tid >> 5] = sq; }
    __syncthreads();
    float tot = 0.f, totq = 0.f;
#pragma unroll
    for (int i = 0; i < 8; i++) { tot += ss[i]; totq += qq[i]; }
    float mu  = tot * (1.f / DD);
    float var = totq * (1.f / DD) - mu * mu;
    float inv = rsqrtf(var + 1e-5f);
    out[base + tid]       = (x0 - mu) * inv * gam[tid]       + bet[tid];
    out[base + tid + 256] = (x1 - mu) * inv * gam[tid + 256] + bet[tid + 256];
}

// ---------------- U = gelu(Au[i] + Bu[j] + Eu[edge]) ----------------
__global__ __launch_bounds__(256) void u_kernel()
{
    int v = blockIdx.x * blockDim.x + threadIdx.x;   // float4 index
    int r  = v >> 7;                                 // edge row (128 f4 per row)
    int d4 = v & 127;
    int bi = r >> 7;
    int b  = r >> 14;
    int bj = (b << 7) + (r & 127);

    const float4* au = (const float4*)(g_nodecat + (size_t)bi * 2560 + 1024) + d4;
    const float4* bu = (const float4*)(g_nodecat + (size_t)bj * 2560 + 1536) + d4;
    const float4* eu = (const float4*)(g_big + (size_t)r * 1024 + 512) + d4;
    float4 A = *au, Bv = *bu, E = *eu;
    float x[4] = {A.x + Bv.x + E.x, A.y + Bv.y + E.y,
                  A.z + Bv.z + E.z, A.w + Bv.w + E.w};
    float o[4];
#pragma unroll
    for (int t = 0; t < 4; t++)
        o[t] = 0.5f * x[t] * (1.f + erff(x[t] * 0.70710678118654752f));
    ((float4*)(g_U + (size_t)r * DD))[d4] = make_float4(o[0], o[1], o[2], o[3]);
}

// ---------------- host ----------------
static float* sym(const void* s) { void* p = nullptr; cudaGetSymbolAddress(&p, s); return (float*)p; }

static void launch_gemm(const float* A, int M, const float* B, int Ntot,
                        float* C, const float* bias, const float* resid) {
    dim3 grid(Ntot / BN, M / BM);
    gemm_mma<<<grid, 256>>>(A, B, C, Ntot, bias, resid);
}

extern "C" void kernel_launch(void* const* d_in, const int* in_sizes, int n_in,
                              void* d_out, int out_size)
{
    const float* node  = (const float*)d_in[0];
    const float* edge  = (const float*)d_in[1];
    const float* adj   = (const float*)d_in[2];
    const float* Wn_w  = (const float*)d_in[3];
    const float* Wn_b  = (const float*)d_in[4];
    const float* We1_w = (const float*)d_in[5];
    const float* We1_b = (const float*)d_in[6];
    const float* We2_w = (const float*)d_in[7];
    const float* We2_b = (const float*)d_in[8];
    const float* Wm_w  = (const float*)d_in[9];
    const float* Wm_b  = (const float*)d_in[10];
    const float* Wu1_w = (const float*)d_in[11];
    const float* Wu1_b = (const float*)d_in[12];
    const float* Wu2_w = (const float*)d_in[13];
    const float* Wu2_b = (const float*)d_in[14];
    const float* Wo_w  = (const float*)d_in[15];
    const float* Wo_b  = (const float*)d_in[16];
    const float* ln_g  = (const float*)d_in[17];
    const float* ln_b  = (const float*)d_in[18];

    float* out_nodes = (float*)d_out;
    float* out_edges = out_nodes + (size_t)NODES * DD;

    float* ph   = sym(g_h);
    float* pCat = sym(g_nodecat);
    float* pAgg = sym(g_agg);
    float* pP   = sym(g_P);
    float* pBig = sym(g_big);
    float* pU   = sym(g_U);
    float* pWb  = sym(g_Wt_big);
    float* pWnc = sym(g_Wt_node);
    float* pWn  = sym(g_Wt_n);
    float* pWo  = sym(g_Wt_o);
    float* pWu2 = sym(g_Wt_u2);
    float* pBn  = sym(g_bnode);

    // weight prep (transpose + rna)
    prep_w<<<dim3(16, 16, 10), dim3(32, 8)>>>(We1_w, Wu1_w, Wm_w, Wn_w, Wo_w, Wu2_w);
    bias_cat<<<10, 256>>>(We1_b, Wu1_b, Wm_b);

    // node projections
    launch_gemm(node, NODES, pWn, DD, ph, Wn_b, nullptr);          // h = node@Wn + b
    launch_gemm(ph, NODES, pWnc, 2560, pCat, pBn, nullptr);        // Ae|Be|Au|Bu|msg

    // big edge GEMM: Ee | Eu
    launch_gemm(edge, EDGES, pWb, 1024, pBig, nullptr, nullptr);

    // attention path
    logits_kernel<<<EDGES / 8, 256>>>(We2_w, We2_b);
    attn_kernel<<<NODES, 256>>>(adj);
    agg_kernel<<<NODES, 256>>>();
    launch_gemm(pAgg, NODES, pWo, DD, pP, Wo_b, nullptr);          // P = agg@Wo + b
    ln_kernel<<<NODES, 256>>>(node, ln_g, ln_b, out_nodes);

    // edge update
    u_kernel<<<(EDGES * (DD / 4)) / 256, 256>>>();
    launch_gemm(pU, EDGES, pWu2, DD, out_edges, Wu2_b, edge);      // edge + U@Wu2 + b
}

// round 9
// speedup vs baseline: 6.0086x; 1.8439x over previous
#include <cuda_runtime.h>
#include <cuda_fp16.h>
#include <math.h>
#include <stdint.h>

// ---------------- problem constants ----------------
#define BB 4
#define NN 128
#define DD 512
#define HH 8
#define NODES (BB * NN)            // 512
#define EDGES (BB * NN * NN)       // 65536
#define KH 512                     // K dim (halfs)

// ---------------- GEMM tile config ----------------
#define BM 128
#define BN 128
#define BKH 64                     // halfs per k-tile (128 B rows)
#define A_TILE 16384               // BM*BKH*2 bytes
#define B_OFF  32768
#define GSMEM  65536

// ---------------- scratch (static __device__) ----------------
__device__ __align__(1024) __half g_node_h[NODES * DD];
__device__ __align__(1024) __half g_edge_h[(size_t)EDGES * DD];
__device__ __align__(1024) __half g_h_h   [NODES * DD];
__device__ __align__(1024) __half g_cat_h [NODES * 2560];   // Ae|Be|Au|Bu|msg
__device__ __align__(1024) __half g_agg_h [NODES * DD];
__device__ __align__(1024) __half g_big_h [(size_t)EDGES * 1024];  // Ee | Eu
__device__ __align__(1024) __half g_U_h   [(size_t)EDGES * DD];
__device__ __align__(1024) float  g_P     [NODES * DD];
__device__ __align__(1024) float  g_logits[EDGES * HH];
__device__ __align__(1024) float  g_attn  [EDGES];
__device__ __align__(1024) __half g_Wn_h  [DD * DD];
__device__ __align__(1024) __half g_Wnc_h [2560 * DD];
__device__ __align__(1024) __half g_Wb_h  [1024 * DD];
__device__ __align__(1024) __half g_Wo_h  [DD * DD];
__device__ __align__(1024) __half g_Wu2_h [DD * DD];
__device__ __align__(1024) float  g_bnode [2560];

// ---------------- helpers ----------------
__device__ __forceinline__ uint32_t smem_u32(const void* p) {
    uint32_t a;
    asm("{ .reg .u64 t; cvta.to.shared.u64 t, %1; cvt.u32.u64 %0, t; }" : "=r"(a) : "l"(p));
    return a;
}
__device__ __forceinline__ void cp16(uint32_t s, const void* g) {
    uint64_t ga = __cvta_generic_to_global(g);
    asm volatile("cp.async.cg.shared.global [%0], [%1], 16;" :: "r"(s), "l"(ga));
}
#define CP_COMMIT() asm volatile("cp.async.commit_group;" ::: "memory")
#define CP_WAIT0()  asm volatile("cp.async.wait_group 0;" ::: "memory")

__device__ __forceinline__ void ldsm4(uint32_t* r, uint32_t addr) {
    asm volatile("ldmatrix.sync.aligned.m8n8.x4.shared.b16 {%0,%1,%2,%3}, [%4];"
        : "=r"(r[0]), "=r"(r[1]), "=r"(r[2]), "=r"(r[3]) : "r"(addr));
}
__device__ __forceinline__ void mma16816(float* c, const uint32_t* a,
                                         uint32_t b0, uint32_t b1) {
    asm volatile(
        "mma.sync.aligned.m16n8k16.row.col.f32.f16.f16.f32 "
        "{%0,%1,%2,%3},{%4,%5,%6,%7},{%8,%9},{%0,%1,%2,%3};"
        : "+f"(c[0]), "+f"(c[1]), "+f"(c[2]), "+f"(c[3])
        : "r"(a[0]), "r"(a[1]), "r"(a[2]), "r"(a[3]), "r"(b0), "r"(b1));
}

// ---------------- FP16 tensor-core GEMM ----------------
// C[M, Ntot] = A[M,512] @ Bw[Ntot,512]^T (+bias) (+resid); out fp32 (Cf) or fp16 (Ch).
__global__ __launch_bounds__(256, 2) void gemm_h(
    const __half* __restrict__ A, const __half* __restrict__ Bw,
    int ldc, const float* __restrict__ bias, const float* __restrict__ resid,
    float* __restrict__ Cf, __half* __restrict__ Ch)
{
    extern __shared__ char dsm[];
    const uint32_t sbase = smem_u32(dsm);

    const int tid = threadIdx.x;
    const int wid = tid >> 5, lane = tid & 31;
    const int g = lane >> 2, tig = lane & 3;
    const int m0 = blockIdx.y * BM, n0 = blockIdx.x * BN;
    const int wm = (wid & 1) * 64, wn = (wid >> 1) * 32;

    float acc[4][4][4];
#pragma unroll
    for (int mi = 0; mi < 4; mi++)
#pragma unroll
        for (int ni = 0; ni < 4; ni++)
#pragma unroll
            for (int j = 0; j < 4; j++) acc[mi][ni][j] = 0.f;

    const int crow = tid >> 3;         // 0..31
    const int cch  = tid & 7;          // chunk (16B) in 128B row

    // tile 0
#pragma unroll
    for (int i = 0; i < 4; i++) {
        int row = crow + i * 32;
        uint32_t sw = (uint32_t)((cch ^ (row & 7)) << 4) + row * 128;
        cp16(sbase + sw,         A  + (size_t)(m0 + row) * KH + cch * 8);
        cp16(sbase + B_OFF + sw, Bw + (size_t)(n0 + row) * KH + cch * 8);
    }
    CP_COMMIT();

    for (int it = 0; it < KH / BKH; it++) {
        CP_WAIT0();
        __syncthreads();
        if (it + 1 < KH / BKH) {
            uint32_t bo = ((it + 1) & 1) * A_TILE;
            int kt = (it + 1) * BKH;
#pragma unroll
            for (int i = 0; i < 4; i++) {
                int row = crow + i * 32;
                uint32_t sw = (uint32_t)((cch ^ (row & 7)) << 4) + row * 128;
                cp16(sbase + bo + sw,         A  + (size_t)(m0 + row) * KH + kt + cch * 8);
                cp16(sbase + B_OFF + bo + sw, Bw + (size_t)(n0 + row) * KH + kt + cch * 8);
            }
            CP_COMMIT();
        }
        const uint32_t sa = sbase + (it & 1) * A_TILE;
        const uint32_t sb = sbase + B_OFF + (it & 1) * A_TILE;
#pragma unroll
        for (int ks = 0; ks < 4; ks++) {
            uint32_t aF[4][4], bF[2][4];
#pragma unroll
            for (int mi = 0; mi < 4; mi++) {
                int mrow = wm + mi * 16 + (lane & 7) + ((lane >> 3) & 1) * 8;
                int kch = ks * 2 + (lane >> 4);
                ldsm4(aF[mi], sa + mrow * 128 + ((kch ^ (mrow & 7)) << 4));
            }
#pragma unroll
            for (int ni2 = 0; ni2 < 2; ni2++) {
                int nrow = wn + ni2 * 16 + (lane & 7) + ((lane >> 4) & 1) * 8;
                int kch = ks * 2 + ((lane >> 3) & 1);
                ldsm4(bF[ni2], sb + nrow * 128 + ((kch ^ (nrow & 7)) << 4));
            }
#pragma unroll
            for (int mi = 0; mi < 4; mi++)
#pragma unroll
                for (int ni = 0; ni < 4; ni++)
                    mma16816(acc[mi][ni], aF[mi],
                             bF[ni >> 1][(ni & 1) * 2], bF[ni >> 1][(ni & 1) * 2 + 1]);
        }
    }

    // epilogue
#pragma unroll
    for (int mi = 0; mi < 4; mi++) {
#pragma unroll
        for (int ni = 0; ni < 4; ni++) {
            int row = m0 + wm + mi * 16 + g;
            int col = n0 + wn + ni * 8 + 2 * tig;
            float2 v0 = make_float2(acc[mi][ni][0], acc[mi][ni][1]);
            float2 v1 = make_float2(acc[mi][ni][2], acc[mi][ni][3]);
            if (bias) {
                float bx = bias[col], by = bias[col + 1];
                v0.x += bx; v0.y += by;
                v1.x += bx; v1.y += by;
            }
            size_t o0 = (size_t)row * ldc + col;
            size_t o1 = (size_t)(row + 8) * ldc + col;
            if (Cf) {
                if (resid) {
                    float2 r0 = *(const float2*)&resid[o0];
                    float2 r1 = *(const float2*)&resid[o1];
                    v0.x += r0.x; v0.y += r0.y;
                    v1.x += r1.x; v1.y += r1.y;
                }
                *(float2*)&Cf[o0] = v0;
                *(float2*)&Cf[o1] = v1;
            } else {
                *(__half2*)&Ch[o0] = __floats2half2_rn(v0.x, v0.y);
                *(__half2*)&Ch[o1] = __floats2half2_rn(v1.x, v1.y);
            }
        }
    }
}

// ---------------- weight prep: transpose 512x512 sections -> fp16 ----------------
__global__ void prep_w(const float* We1, const float* Wu1, const float* Wm,
                       const float* Wn, const float* Wo, const float* Wu2)
{
    int z = blockIdx.z;
    const float* src; __half* dst;
    switch (z) {
        case 0: src = We1 + 1024 * DD; dst = g_Wb_h;              break;
        case 1: src = Wu1 + 1024 * DD; dst = g_Wb_h + 512 * DD;   break;
        case 2: src = We1;             dst = g_Wnc_h;             break;
        case 3: src = We1 + 512 * DD;  dst = g_Wnc_h + 512 * DD;  break;
        case 4: src = Wu1;             dst = g_Wnc_h + 1024 * DD; break;
        case 5: src = Wu1 + 512 * DD;  dst = g_Wnc_h + 1536 * DD; break;
        case 6: src = Wm;              dst = g_Wnc_h + 2048 * DD; break;
        case 7: src = Wn;              dst = g_Wn_h;  break;
        case 8: src = Wo;              dst = g_Wo_h;  break;
        default: src = Wu2;            dst = g_Wu2_h; break;
    }
    __shared__ float t[32][33];
    int bx = blockIdx.x * 32, by = blockIdx.y * 32;
    for (int i = threadIdx.y; i < 32; i += 8)
        t[i][threadIdx.x] = src[(size_t)(by + i) * DD + bx + threadIdx.x];
    __syncthreads();
    for (int i = threadIdx.y; i < 32; i += 8)
        dst[(size_t)(bx + i) * DD + by + threadIdx.x] = __float2half(t[threadIdx.x][i]);
}

__global__ void bias_cat(const float* We1_b, const float* Wu1_b, const float* Wm_b)
{
    int i = blockIdx.x * blockDim.x + threadIdx.x;
    if (i >= 2560) return;
    float v = 0.f;
    if (i < 512) v = We1_b[i];
    else if (i >= 1024 && i < 1536) v = Wu1_b[i - 1024];
    else if (i >= 2048) v = Wm_b[i - 2048];
    g_bnode[i] = v;
}

// ---------------- fp32 -> fp16 bulk convert (8 elems / thread) ----------------
__global__ void conv_half(const float* __restrict__ src, __half* __restrict__ dst, int n8)
{
    int i = blockIdx.x * blockDim.x + threadIdx.x;
    if (i >= n8) return;
    float4 v0 = ((const float4*)src)[2 * i];
    float4 v1 = ((const float4*)src)[2 * i + 1];
    __half2 h[4];
    h[0] = __floats2half2_rn(v0.x, v0.y);
    h[1] = __floats2half2_rn(v0.z, v0.w);
    h[2] = __floats2half2_rn(v1.x, v1.y);
    h[3] = __floats2half2_rn(v1.z, v1.w);
    ((uint4*)dst)[i] = *(uint4*)h;
}

// ---------------- edge attention logits: one warp per edge ----------------
__global__ __launch_bounds__(256) void logits_kernel(
    const float* __restrict__ We2_w, const float* __restrict__ We2_b)
{
    int warp = (blockIdx.x * blockDim.x + threadIdx.x) >> 5;
    int lane = threadIdx.x & 31;
    if (warp >= EDGES) return;
    int r  = warp;
    int bi = r >> 7;
    int b  = r >> 14;
    int bj = (b << 7) + (r & 127);

    const __half* ae = g_cat_h + (size_t)bi * 2560;         // Ae
    const __half* be = g_cat_h + (size_t)bj * 2560 + 512;   // Be
    const __half* ee = g_big_h + (size_t)r * 1024;          // Ee

    float acc[HH];
#pragma unroll
    for (int h = 0; h < HH; h++) acc[h] = 0.f;

    for (int d = lane * 2; d < DD; d += 64) {
        __half2 a2 = *(const __half2*)&ae[d];
        __half2 b2 = *(const __half2*)&be[d];
        __half2 e2 = *(const __half2*)&ee[d];
        float x0 = __low2float(a2) + __low2float(b2) + __low2float(e2);
        float x1 = __high2float(a2) + __high2float(b2) + __high2float(e2);
        float e0 = (x0 > 0.f) ? x0 : 0.2f * x0;
        float e1 = (x1 > 0.f) ? x1 : 0.2f * x1;
        const float* w0 = We2_w + (size_t)d * HH;
        const float* w1 = w0 + HH;
        float4 wa = *(const float4*)w0;
        float4 wb = *(const float4*)(w0 + 4);
        float4 wc = *(const float4*)w1;
        float4 wd = *(const float4*)(w1 + 4);
        acc[0] += e0 * wa.x + e1 * wc.x; acc[1] += e0 * wa.y + e1 * wc.y;
        acc[2] += e0 * wa.z + e1 * wc.z; acc[3] += e0 * wa.w + e1 * wc.w;
        acc[4] += e0 * wb.x + e1 * wd.x; acc[5] += e0 * wb.y + e1 * wd.y;
        acc[6] += e0 * wb.z + e1 * wd.z; acc[7] += e0 * wb.w + e1 * wd.w;
    }
#pragma unroll
    for (int h = 0; h < HH; h++) {
#pragma unroll
        for (int off = 16; off; off >>= 1)
            acc[h] += __shfl_xor_sync(0xffffffffu, acc[h], off);
    }
    if (lane < HH) g_logits[(size_t)r * HH + lane] = acc[lane] + We2_b[lane];
}

// ---------------- softmax over j, * adj, mean over heads ----------------
__global__ __launch_bounds__(256) void attn_kernel(const float* __restrict__ adj)
{
    int bi = blockIdx.x;
    __shared__ float L[NN][HH];
    __shared__ float mx[HH], sm[HH];
    int tid = threadIdx.x;
    for (int t = tid; t < NN * HH; t += 256)
        ((float*)L)[t] = g_logits[(size_t)bi * NN * HH + t];
    __syncthreads();
    if (tid < HH) {
        float m = -1e30f;
        for (int j = 0; j < NN; j++) m = fmaxf(m, L[j][tid]);
        float s = 0.f;
        for (int j = 0; j < NN; j++) s += expf(L[j][tid] - m);
        mx[tid] = m; sm[tid] = 1.f / s;
    }
    __syncthreads();
    if (tid < NN) {
        float acc = 0.f;
#pragma unroll
        for (int h = 0; h < HH; h++) acc += expf(L[tid][h] - mx[h]) * sm[h];
        g_attn[(size_t)bi * NN + tid] = adj[(size_t)bi * NN + tid] * acc * (1.f / HH);
    }
}

// ---------------- aggregated = attn_mean @ messages (fp16 out) ----------------
__global__ __launch_bounds__(256) void agg_kernel()
{
    int bi = blockIdx.x;
    int b  = bi >> 7;
    __shared__ float a[NN];
    int tid = threadIdx.x;
    if (tid < NN) a[tid] = g_attn[(size_t)bi * NN + tid];
    __syncthreads();
    for (int d = tid; d < DD; d += 256) {
        float acc = 0.f;
#pragma unroll 4
        for (int j = 0; j < NN; j++)
            acc += a[j] * __half2float(g_cat_h[(size_t)((b << 7) + j) * 2560 + 2048 + d]);
        g_agg_h[(size_t)bi * DD + d] = __float2half(acc);
    }
}

// ---------------- LayerNorm(node + P) ----------------
__global__ __launch_bounds__(256) void ln_kernel(
    const float* __restrict__ node, const float* __restrict__ gam,
    const float* __restrict__ bet, float* __restrict__ out)
{
    int bi = blockIdx.x;
    int tid = threadIdx.x;
    size_t base = (size_t)bi * DD;
    float x0 = node[base + tid]       + g_P[base + tid];
    float x1 = node[base + tid + 256] + g_P[base + tid + 256];
    float s  = x0 + x1;
    float sq = x0 * x0 + x1 * x1;
    __shared__ float ss[8], qq[8];
#pragma unroll
    for (int o = 16; o; o >>= 1) {
        s  += __shfl_xor_sync(0xffffffffu, s,  o);
        sq += __shfl_xor_sync(0xffffffffu, sq, o);
    }
    if ((tid & 31) == 0) { ss[tid >> 5] = s; qq[tid >> 5] = sq; }
    __syncthreads();
    float tot = 0.f, totq = 0.f;
#pragma unroll
    for (int i = 0; i < 8; i++) { tot += ss[i]; totq += qq[i]; }
    float mu  = tot * (1.f / DD);
    float var = totq * (1.f / DD) - mu * mu;
    float inv = rsqrtf(var + 1e-5f);
    out[base + tid]       = (x0 - mu) * inv * gam[tid]       + bet[tid];
    out[base + tid + 256] = (x1 - mu) * inv * gam[tid + 256] + bet[tid + 256];
}

// ---------------- U = gelu(Au[i] + Bu[j] + Eu[edge]) -> fp16 ----------------
__global__ __launch_bounds__(256) void u_kernel()
{
    int idx = blockIdx.x * blockDim.x + threadIdx.x;   // 8-half groups
    int r  = idx >> 6;                                 // 64 groups per edge row
    int d8 = (idx & 63) * 8;
    int bi = r >> 7;
    int b  = r >> 14;
    int bj = (b << 7) + (r & 127);

    uint4 au = *(const uint4*)(g_cat_h + (size_t)bi * 2560 + 1024 + d8);
    uint4 bu = *(const uint4*)(g_cat_h + (size_t)bj * 2560 + 1536 + d8);
    uint4 eu = *(const uint4*)(g_big_h + (size_t)r * 1024 + 512 + d8);
    const __half2* a2 = (const __half2*)&au;
    const __half2* b2 = (const __half2*)&bu;
    const __half2* e2 = (const __half2*)&eu;
    __half2 o[4];
#pragma unroll
    for (int t = 0; t < 4; t++) {
        float x0 = __low2float(a2[t]) + __low2float(b2[t]) + __low2float(e2[t]);
        float x1 = __high2float(a2[t]) + __high2float(b2[t]) + __high2float(e2[t]);
        float g0 = 0.5f * x0 * (1.f + erff(x0 * 0.70710678118654752f));
        float g1 = 0.5f * x1 * (1.f + erff(x1 * 0.70710678118654752f));
        o[t] = __floats2half2_rn(g0, g1);
    }
    *(uint4*)(g_U_h + (size_t)r * DD + d8) = *(uint4*)o;
}

// ---------------- host ----------------
static void* symv(const void* s) { void* p = nullptr; cudaGetSymbolAddress(&p, s); return p; }

static void launch_gemm(const __half* A, int M, const __half* B, int Ntot,
                        const float* bias, const float* resid,
                        float* Cf, __half* Ch) {
    dim3 grid(Ntot / BN, M / BM);
    gemm_h<<<grid, 256, GSMEM>>>(A, B, Ntot, bias, resid, Cf, Ch);
}

extern "C" void kernel_launch(void* const* d_in, const int* in_sizes, int n_in,
                              void* d_out, int out_size)
{
    const float* node  = (const float*)d_in[0];
    const float* edge  = (const float*)d_in[1];
    const float* adj   = (const float*)d_in[2];
    const float* Wn_w  = (const float*)d_in[3];
    const float* Wn_b  = (const float*)d_in[4];
    const float* We1_w = (const float*)d_in[5];
    const float* We1_b = (const float*)d_in[6];
    const float* We2_w = (const float*)d_in[7];
    const float* We2_b = (const float*)d_in[8];
    const float* Wm_w  = (const float*)d_in[9];
    const float* Wm_b  = (const float*)d_in[10];
    const float* Wu1_w = (const float*)d_in[11];
    const float* Wu1_b = (const float*)d_in[12];
    const float* Wu2_w = (const float*)d_in[13];
    const float* Wu2_b = (const float*)d_in[14];
    const float* Wo_w  = (const float*)d_in[15];
    const float* Wo_b  = (const float*)d_in[16];
    const float* ln_g  = (const float*)d_in[17];
    const float* ln_b  = (const float*)d_in[18];

    float* out_nodes = (float*)d_out;
    float* out_edges = out_nodes + (size_t)NODES * DD;

    cudaFuncSetAttribute(gemm_h, cudaFuncAttributeMaxDynamicSharedMemorySize, GSMEM);

    __half* pNodeH = (__half*)symv(g_node_h);
    __half* pEdgeH = (__half*)symv(g_edge_h);
    __half* pH     = (__half*)symv(g_h_h);
    __half* pCat   = (__half*)symv(g_cat_h);
    __half* pAgg   = (__half*)symv(g_agg_h);
    __half* pBig   = (__half*)symv(g_big_h);
    __half* pU     = (__half*)symv(g_U_h);
    float*  pP     = (float*)symv(g_P);
    __half* pWn    = (__half*)symv(g_Wn_h);
    __half* pWnc   = (__half*)symv(g_Wnc_h);
    __half* pWb    = (__half*)symv(g_Wb_h);
    __half* pWo    = (__half*)symv(g_Wo_h);
    __half* pWu2   = (__half*)symv(g_Wu2_h);
    float*  pBn    = (float*)symv(g_bnode);

    // prep: weights (transpose + fp16), biases, input conversions
    prep_w<<<dim3(16, 16, 10), dim3(32, 8)>>>(We1_w, Wu1_w, Wm_w, Wn_w, Wo_w, Wu2_w);
    bias_cat<<<10, 256>>>(We1_b, Wu1_b, Wm_b);
    conv_half<<<(NODES * DD / 8 + 255) / 256, 256>>>(node, pNodeH, NODES * DD / 8);
    conv_half<<<((int)((size_t)EDGES * DD / 8) + 255) / 256, 256>>>(
        edge, pEdgeH, (int)((size_t)EDGES * DD / 8));

    // node projections
    launch_gemm(pNodeH, NODES, pWn, DD, Wn_b, nullptr, nullptr, pH);     // h
    launch_gemm(pH, NODES, pWnc, 2560, pBn, nullptr, nullptr, pCat);     // Ae|Be|Au|Bu|msg

    // big edge GEMM: Ee | Eu
    launch_gemm(pEdgeH, EDGES, pWb, 1024, nullptr, nullptr, nullptr, pBig);

    // attention path
    logits_kernel<<<EDGES / 8, 256>>>(We2_w, We2_b);
    attn_kernel<<<NODES, 256>>>(adj);
    agg_kernel<<<NODES, 256>>>();
    launch_gemm(pAgg, NODES, pWo, DD, Wo_b, nullptr, pP, nullptr);       // P
    ln_kernel<<<NODES, 256>>>(node, ln_g, ln_b, out_nodes);

    // edge update
    u_kernel<<<(int)((size_t)EDGES * 64 / 256), 256>>>();
    launch_gemm(pU, EDGES, pWu2, DD, Wu2_b, edge, out_edges, nullptr);   // edge + U@Wu2 + b
}